// round 12
// baseline (speedup 1.0000x reference)
#include <cuda_runtime.h>
#include <cuda_fp16.h>
#include <cstdint>

// Problem constants
#define M_DIM 8192
#define N_DIM 4096
#define K_DIM 4096
#define RANK  16

// GEMM tiling: block 128x256, 8 warps, warp tile 64x64 (R5 layout), 6 stages
#define BM 128
#define BN 256
#define BK 32                        // fp16 elems per k-tile
#define NT (K_DIM / BK)              // 128 k-iterations
#define NSS (NT / 2)                 // 64 supersteps
#define NSTAGE 6
#define RS 40                        // smem row stride in halves (32 + 8 pad)
#define RSB (RS * 2)                 // 80 bytes
#define A_ST_BYTES (BM * RSB)        // 10240
#define B_ST_BYTES (BN * RSB)        // 20480
#define STAGE_BYTES (A_ST_BYTES + B_ST_BYTES)   // 30720
#define SMEM_TOTAL (NSTAGE * STAGE_BYTES)       // 184320

// Pre-converted fp16 operands (device globals: allocation-free rule)
__device__ __half g_xh[(size_t)M_DIM * K_DIM];
__device__ __half g_wh[(size_t)N_DIM * K_DIM];

// ---------------------------------------------------------------------------
// PTX helpers (baseline ISA only)
// ---------------------------------------------------------------------------
__device__ __forceinline__ uint32_t smem_to_u32(const void* p) {
    uint32_t a;
    asm("{ .reg .u64 t; cvta.to.shared.u64 t, %1; cvt.u32.u64 %0, t; }" : "=r"(a) : "l"(p));
    return a;
}
#define CP_ASYNC16(dst, src) \
    asm volatile("cp.async.cg.shared.global [%0], [%1], 16;" :: "r"(dst), "l"(src))
#define CP_COMMIT() asm volatile("cp.async.commit_group;")
#define CP_WAIT(n)  asm volatile("cp.async.wait_group %0;" :: "n"(n))

#define LDSM_X4(r, addr) \
    asm volatile("ldmatrix.sync.aligned.m8n8.x4.shared.b16 {%0,%1,%2,%3}, [%4];" \
                 : "=r"((r)[0]), "=r"((r)[1]), "=r"((r)[2]), "=r"((r)[3]) : "r"(addr))

#define MMA_F16(d, a, b0, b1) \
    asm volatile("mma.sync.aligned.m16n8k16.row.col.f32.f16.f16.f32 " \
                 "{%0,%1,%2,%3}, {%4,%5,%6,%7}, {%8,%9}, {%0,%1,%2,%3};" \
                 : "+f"((d)[0]), "+f"((d)[1]), "+f"((d)[2]), "+f"((d)[3]) \
                 : "r"((a)[0]), "r"((a)[1]), "r"((a)[2]), "r"((a)[3]), "r"(b0), "r"(b1))

// ---------------------------------------------------------------------------
// Kernel 1 (merged prologue): convert x -> fp16 AND fold W_eff -> fp16.
// ---------------------------------------------------------------------------
#define XBLK ((int)(((size_t)M_DIM * K_DIM) / 4 / 256))   // 32768
#define WBLK ((int)(((size_t)N_DIM * K_DIM) / 4 / 256))   // 16384

__global__ void prologue_kernel(const float* __restrict__ x,
                                const float* __restrict__ W,
                                const float* __restrict__ w1a,
                                const float* __restrict__ w1b,
                                const float* __restrict__ w2a,
                                const float* __restrict__ w2b,
                                const float* __restrict__ scalar) {
    if (blockIdx.x < XBLK) {
        size_t i = (size_t)(blockIdx.x * 256 + threadIdx.x) * 4;
        float4 v = *(const float4*)(x + i);
        __half2* o = (__half2*)(g_xh + i);
        o[0] = __floats2half2_rn(v.x, v.y);
        o[1] = __floats2half2_rn(v.z, v.w);
    } else {
        size_t idx = (size_t)((blockIdx.x - XBLK) * 256 + threadIdx.x) * 4;
        int o = (int)(idx >> 12);
        int i = (int)(idx & 4095);
        float4 s1 = {0.f, 0.f, 0.f, 0.f};
        float4 s2 = {0.f, 0.f, 0.f, 0.f};
#pragma unroll
        for (int r = 0; r < RANK; ++r) {
            float a1 = w1a[o * RANK + r];
            float a2 = w2a[o * RANK + r];
            float4 b1 = *(const float4*)(w1b + (size_t)r * K_DIM + i);
            float4 b2 = *(const float4*)(w2b + (size_t)r * K_DIM + i);
            s1.x += a1 * b1.x; s1.y += a1 * b1.y; s1.z += a1 * b1.z; s1.w += a1 * b1.w;
            s2.x += a2 * b2.x; s2.y += a2 * b2.y; s2.z += a2 * b2.z; s2.w += a2 * b2.w;
        }
        float sc = scalar[0];
        float4 w = *(const float4*)(W + idx);
        __half2* out = (__half2*)(g_wh + idx);
        out[0] = __floats2half2_rn(w.x + s1.x * s2.x * sc, w.y + s1.y * s2.y * sc);
        out[1] = __floats2half2_rn(w.z + s1.z * s2.z * sc, w.w + s1.w * s2.w * sc);
    }
}

// ---------------------------------------------------------------------------
// Kernel 2: Y = Xh @ Wh^T + bias. 256 threads, warp grid 2(M) x 4(N),
// warp tile 64x64. 6-stage, 2-kt superstep, CP_WAIT(1) (one group in flight).
// ---------------------------------------------------------------------------
__global__ void __launch_bounds__(256, 1)
gemm_f16_kernel(const float* __restrict__ bias, float* __restrict__ Y) {
    extern __shared__ char smem[];
    const uint32_t sb0 = smem_to_u32(smem);
    const int tid = threadIdx.x;
    const int l = tid & 31;
    const int warp = tid >> 5;
    const int wm = warp & 1;     // 2 warps along M (64 rows)
    const int wn = warp >> 1;    // 4 warps along N (64 cols)

    // tile coords with 8-row supertile swizzle for L2 reuse
    const int bid = blockIdx.x;
    const int sbt = bid >> 7;
    const int rr = bid & 127;
    const int m0 = ((sbt << 3) + (rr & 7)) * BM;
    const int n0 = (rr >> 3) * BN;

    const __half* Xg = g_xh + (size_t)m0 * K_DIM;
    const __half* Wg = g_wh + (size_t)n0 * K_DIM;

    // cp.async mapping: 256 threads -> (row 0..63, 16B chunk 0..3)
    const int crow = tid >> 2;
    const int cchk = tid & 3;
    const uint32_t a_dst = (uint32_t)crow * RSB + cchk * 16;
    const __half* a_src = Xg + (size_t)crow * K_DIM + cchk * 8;
    const uint32_t b_dst = A_ST_BYTES + (uint32_t)crow * RSB + cchk * 16;
    const __half* b_src = Wg + (size_t)crow * K_DIM + cchk * 8;

    // ldmatrix lane address components
    const uint32_t lrow = l & 15;
    const uint32_t lkof = (uint32_t)(l >> 4) * 16;
    const uint32_t a_lane = (uint32_t)(wm * 64 + lrow) * RSB + lkof;
    const uint32_t b_lane = A_ST_BYTES + (uint32_t)(wn * 64 + lrow) * RSB + lkof;

    float acc[4][8][4];
#pragma unroll
    for (int a = 0; a < 4; ++a)
#pragma unroll
        for (int b = 0; b < 8; ++b)
#pragma unroll
            for (int c = 0; c < 4; ++c) acc[a][b][c] = 0.f;

#define ISSUE_STAGE(ss_, kk_) do { \
        const uint32_t _sa = sb0 + (uint32_t)(ss_) * STAGE_BYTES; \
        CP_ASYNC16(_sa + a_dst, a_src + (kk_) * BK); \
        CP_ASYNC16(_sa + a_dst + 64 * RSB, a_src + (size_t)64 * K_DIM + (kk_) * BK); \
        _Pragma("unroll") \
        for (int _i = 0; _i < 4; ++_i) \
            CP_ASYNC16(_sa + b_dst + (uint32_t)_i * 64 * RSB, \
                       b_src + (size_t)_i * 64 * K_DIM + (kk_) * BK); \
    } while (0)

#define LDSM_SET(buf, sa, koff) do { \
        _Pragma("unroll") \
        for (int _mi = 0; _mi < 4; ++_mi) \
            LDSM_X4(fa[buf][_mi], (sa) + a_lane + (uint32_t)_mi * 16 * RSB + (koff)); \
        _Pragma("unroll") \
        for (int _bi = 0; _bi < 4; ++_bi) \
            LDSM_X4(fb[buf][_bi], (sa) + b_lane + (uint32_t)_bi * 16 * RSB + (koff)); \
    } while (0)

#define MMA_SET(buf) do { \
        _Pragma("unroll") \
        for (int _mi = 0; _mi < 4; ++_mi) \
            _Pragma("unroll") \
            for (int _bi = 0; _bi < 4; ++_bi) { \
                MMA_F16(acc[_mi][2 * _bi],     fa[buf][_mi], fb[buf][_bi][0], fb[buf][_bi][2]); \
                MMA_F16(acc[_mi][2 * _bi + 1], fa[buf][_mi], fb[buf][_bi][1], fb[buf][_bi][3]); \
            } \
    } while (0)

    // ---- prologue: stages 0,1 as group G0; stages 2,3 as group G1 ----
    ISSUE_STAGE(0, 0);
    ISSUE_STAGE(1, 1);
    CP_COMMIT();
    ISSUE_STAGE(2, 2);
    ISSUE_STAGE(3, 3);
    CP_COMMIT();
    CP_WAIT(1);                   // stages 0,1 resident; G1 in flight
    __syncthreads();

    uint32_t fa[2][4][4], fb[2][4][4];
    LDSM_SET(0, sb0, 0);          // stage 0, ks0

    // rotating stage slots (mod 6): cur0, cur0+1=cur1, cur0+2=nx0, issue at +4,+5
    int sl = 0;                   // slot of kt0

    // ---- main loop: 64 supersteps ----
    for (int ss = 0; ss < NSS; ++ss) {
        const int kt0 = 2 * ss;
        int sl1 = sl + 1; if (sl1 >= NSTAGE) sl1 -= NSTAGE;
        int sl2 = sl + 2; if (sl2 >= NSTAGE) sl2 -= NSTAGE;
        int sl4 = sl + 4; if (sl4 >= NSTAGE) sl4 -= NSTAGE;
        int sl5 = sl + 5; if (sl5 >= NSTAGE) sl5 -= NSTAGE;
        const uint32_t s_cur0 = sb0 + (uint32_t)sl  * STAGE_BYTES;
        const uint32_t s_cur1 = sb0 + (uint32_t)sl1 * STAGE_BYTES;
        const uint32_t s_nx0  = sb0 + (uint32_t)sl2 * STAGE_BYTES;

        // issue loads for stages kt0+4, kt0+5 (one commit group)
        if (ss < NSS - 2) {
            ISSUE_STAGE(sl4, kt0 + 4);
            ISSUE_STAGE(sl5, kt0 + 5);
            CP_COMMIT();
        }

        // 3 half-steps before the barrier
        LDSM_SET(1, s_cur0, 32);  MMA_SET(0);   // cur0 ks0
        LDSM_SET(0, s_cur1, 0);   MMA_SET(1);   // cur0 ks1
        LDSM_SET(1, s_cur1, 32);  MMA_SET(0);   // cur1 ks0

        // wait: stages kt0+2, kt0+3 resident (group from previous superstep)
        if (ss < NSS - 2) { CP_WAIT(1); } else { CP_WAIT(0); }
        __syncthreads();

        if (ss < NSS - 1) {
            LDSM_SET(0, s_nx0, 0);                 // prefetch next superstep ks0
        }
        MMA_SET(1);                                // cur1 ks1

        sl = sl2;
    }

    // ---- epilogue: add bias, write fp32 ----
    const int g = l >> 2;
    const int t = l & 3;
#pragma unroll
    for (int mi = 0; mi < 4; ++mi) {
        const int row0 = m0 + wm * 64 + mi * 16 + g;
        float* y0 = Y + (size_t)row0 * N_DIM;
#pragma unroll
        for (int ni = 0; ni < 8; ++ni) {
            const int col = n0 + wn * 64 + (ni >> 1) * 16 + (ni & 1) * 8 + 2 * t;
            const float2 bv = *(const float2*)(bias + col);
            float2 o0, o1;
            o0.x = acc[mi][ni][0] + bv.x;  o0.y = acc[mi][ni][1] + bv.y;
            o1.x = acc[mi][ni][2] + bv.x;  o1.y = acc[mi][ni][3] + bv.y;
            *(float2*)(y0 + col) = o0;
            *(float2*)(y0 + (size_t)8 * N_DIM + col) = o1;   // rows g+8
        }
    }
}

// ---------------------------------------------------------------------------
extern "C" void kernel_launch(void* const* d_in, const int* in_sizes, int n_in,
                              void* d_out, int out_size) {
    const float* x      = (const float*)d_in[0];
    const float* W      = (const float*)d_in[1];
    const float* bias   = (const float*)d_in[2];
    const float* w1a    = (const float*)d_in[3];
    const float* w1b    = (const float*)d_in[4];
    const float* w2a    = (const float*)d_in[5];
    const float* w2b    = (const float*)d_in[6];
    const float* scalar = (const float*)d_in[7];
    float* y = (float*)d_out;

    prologue_kernel<<<XBLK + WBLK, 256>>>(x, W, w1a, w1b, w2a, w2b, scalar);

    cudaFuncSetAttribute(gemm_f16_kernel,
                         cudaFuncAttributeMaxDynamicSharedMemorySize, SMEM_TOTAL);
    const int nblocks = (M_DIM / BM) * (N_DIM / BN);   // 1024
    gemm_f16_kernel<<<nblocks, 256, SMEM_TOTAL>>>(bias, y);
}

// round 15
// speedup vs baseline: 1.2571x; 1.2571x over previous
#include <cuda_runtime.h>
#include <cuda_fp16.h>
#include <cstdint>

// Problem constants
#define M_DIM 8192
#define N_DIM 4096
#define K_DIM 4096
#define RANK  16

// GEMM tiling: block 128x256, 8 warps, warp tile 64x64 (validated R5 layout)
#define BM 128
#define BN 256
#define BK 32                        // fp16 elems per k-tile
#define NT (K_DIM / BK)              // 128 k-iterations
#define NSTAGE 5
#define RS 40                        // smem row stride in halves (32 + 8 pad)
#define RSB (RS * 2)                 // 80 bytes
#define A_ST_BYTES (BM * RSB)        // 10240
#define B_ST_BYTES (BN * RSB)        // 20480
#define STAGE_BYTES (A_ST_BYTES + B_ST_BYTES)   // 30720
#define SMEM_TOTAL (NSTAGE * STAGE_BYTES)       // 153600

// Pre-converted fp16 operands (device globals: allocation-free rule)
__device__ __half g_xh[(size_t)M_DIM * K_DIM];
__device__ __half g_wh[(size_t)N_DIM * K_DIM];

// ---------------------------------------------------------------------------
// PTX helpers (baseline ISA only)
// ---------------------------------------------------------------------------
__device__ __forceinline__ uint32_t smem_to_u32(const void* p) {
    uint32_t a;
    asm("{ .reg .u64 t; cvta.to.shared.u64 t, %1; cvt.u32.u64 %0, t; }" : "=r"(a) : "l"(p));
    return a;
}
#define CP_ASYNC16(dst, src) \
    asm volatile("cp.async.cg.shared.global [%0], [%1], 16;" :: "r"(dst), "l"(src))
#define CP_COMMIT() asm volatile("cp.async.commit_group;")
#define CP_WAIT(n)  asm volatile("cp.async.wait_group %0;" :: "n"(n))

#define LDSM_X4(r, addr) \
    asm volatile("ldmatrix.sync.aligned.m8n8.x4.shared.b16 {%0,%1,%2,%3}, [%4];" \
                 : "=r"((r)[0]), "=r"((r)[1]), "=r"((r)[2]), "=r"((r)[3]) : "r"(addr))

#define MMA_F16(d, a, b0, b1) \
    asm volatile("mma.sync.aligned.m16n8k16.row.col.f32.f16.f16.f32 " \
                 "{%0,%1,%2,%3}, {%4,%5,%6,%7}, {%8,%9}, {%0,%1,%2,%3};" \
                 : "+f"((d)[0]), "+f"((d)[1]), "+f"((d)[2]), "+f"((d)[3]) \
                 : "r"((a)[0]), "r"((a)[1]), "r"((a)[2]), "r"((a)[3]), "r"(b0), "r"(b1))

// ---------------------------------------------------------------------------
// Kernel 1 (merged prologue): convert x -> fp16 AND fold W_eff -> fp16.
// ---------------------------------------------------------------------------
#define XBLK ((int)(((size_t)M_DIM * K_DIM) / 4 / 256))   // 32768
#define WBLK ((int)(((size_t)N_DIM * K_DIM) / 4 / 256))   // 16384

__global__ void prologue_kernel(const float* __restrict__ x,
                                const float* __restrict__ W,
                                const float* __restrict__ w1a,
                                const float* __restrict__ w1b,
                                const float* __restrict__ w2a,
                                const float* __restrict__ w2b,
                                const float* __restrict__ scalar) {
    if (blockIdx.x < XBLK) {
        size_t i = (size_t)(blockIdx.x * 256 + threadIdx.x) * 4;
        float4 v = *(const float4*)(x + i);
        __half2* o = (__half2*)(g_xh + i);
        o[0] = __floats2half2_rn(v.x, v.y);
        o[1] = __floats2half2_rn(v.z, v.w);
    } else {
        size_t idx = (size_t)((blockIdx.x - XBLK) * 256 + threadIdx.x) * 4;
        int o = (int)(idx >> 12);
        int i = (int)(idx & 4095);
        float4 s1 = {0.f, 0.f, 0.f, 0.f};
        float4 s2 = {0.f, 0.f, 0.f, 0.f};
#pragma unroll
        for (int r = 0; r < RANK; ++r) {
            float a1 = w1a[o * RANK + r];
            float a2 = w2a[o * RANK + r];
            float4 b1 = *(const float4*)(w1b + (size_t)r * K_DIM + i);
            float4 b2 = *(const float4*)(w2b + (size_t)r * K_DIM + i);
            s1.x += a1 * b1.x; s1.y += a1 * b1.y; s1.z += a1 * b1.z; s1.w += a1 * b1.w;
            s2.x += a2 * b2.x; s2.y += a2 * b2.y; s2.z += a2 * b2.z; s2.w += a2 * b2.w;
        }
        float sc = scalar[0];
        float4 w = *(const float4*)(W + idx);
        __half2* out = (__half2*)(g_wh + idx);
        out[0] = __floats2half2_rn(w.x + s1.x * s2.x * sc, w.y + s1.y * s2.y * sc);
        out[1] = __floats2half2_rn(w.z + s1.z * s2.z * sc, w.w + s1.w * s2.w * sc);
    }
}

// ---------------------------------------------------------------------------
// Kernel 2: Y = Xh @ Wh^T + bias. 256 threads, warp grid 2(M) x 4(N),
// warp tile 64x64, register-double-buffered fragments. (R5 structure)
// ---------------------------------------------------------------------------
__global__ void __launch_bounds__(256, 1)
gemm_f16_kernel(const float* __restrict__ bias, float* __restrict__ Y) {
    extern __shared__ char smem[];
    const uint32_t sb0 = smem_to_u32(smem);
    const int tid = threadIdx.x;
    const int l = tid & 31;
    const int warp = tid >> 5;
    const int wm = warp & 1;     // 2 warps along M (64 rows)
    const int wn = warp >> 1;    // 4 warps along N (64 cols)

    // tile coords with 8-row supertile swizzle for L2 reuse
    const int bid = blockIdx.x;
    const int sbt = bid >> 7;
    const int rr = bid & 127;
    const int m0 = ((sbt << 3) + (rr & 7)) * BM;
    const int n0 = (rr >> 3) * BN;

    const __half* Xg = g_xh + (size_t)m0 * K_DIM;
    const __half* Wg = g_wh + (size_t)n0 * K_DIM;

    // cp.async mapping: 256 threads -> (row 0..63, 16B chunk 0..3)
    const int crow = tid >> 2;
    const int cchk = tid & 3;
    const uint32_t a_dst = (uint32_t)crow * RSB + cchk * 16;
    const __half* a_src = Xg + (size_t)crow * K_DIM + cchk * 8;
    const uint32_t b_dst = A_ST_BYTES + (uint32_t)crow * RSB + cchk * 16;
    const __half* b_src = Wg + (size_t)crow * K_DIM + cchk * 8;

    // ldmatrix lane address components
    const uint32_t lrow = l & 15;
    const uint32_t lkof = (uint32_t)(l >> 4) * 16;
    const uint32_t a_lane = (uint32_t)(wm * 64 + lrow) * RSB + lkof;
    const uint32_t b_lane = A_ST_BYTES + (uint32_t)(wn * 64 + lrow) * RSB + lkof;

    float acc[4][8][4];
#pragma unroll
    for (int a = 0; a < 4; ++a)
#pragma unroll
        for (int b = 0; b < 8; ++b)
#pragma unroll
            for (int c = 0; c < 4; ++c) acc[a][b][c] = 0.f;

    // ---- pipeline prologue: load stages 0..NSTAGE-2 ----
#pragma unroll
    for (int s = 0; s < NSTAGE - 1; ++s) {
        const uint32_t sa = sb0 + s * STAGE_BYTES;
        CP_ASYNC16(sa + a_dst, a_src + s * BK);
        CP_ASYNC16(sa + a_dst + 64 * RSB, a_src + (size_t)64 * K_DIM + s * BK);
#pragma unroll
        for (int i = 0; i < 4; ++i)
            CP_ASYNC16(sa + b_dst + (uint32_t)i * 64 * RSB,
                       b_src + (size_t)i * 64 * K_DIM + s * BK);
        CP_COMMIT();
    }
    CP_WAIT(NSTAGE - 2);
    __syncthreads();

    uint32_t fa[2][4][4], fb[2][4][4];

    // fragments for stage 0, ks 0
#pragma unroll
    for (int mi = 0; mi < 4; ++mi)
        LDSM_X4(fa[0][mi], sb0 + a_lane + (uint32_t)mi * 16 * RSB);
#pragma unroll
    for (int bi = 0; bi < 4; ++bi)
        LDSM_X4(fb[0][bi], sb0 + b_lane + (uint32_t)bi * 16 * RSB);

    // ---- main loop (R5 structure, NSTAGE=5) ----
    for (int kt = 0; kt < NT; ++kt) {
        const uint32_t sa = sb0 + (uint32_t)(kt % NSTAGE) * STAGE_BYTES;

        // issue gmem->smem for stage kt+NSTAGE-1
        const int nk = kt + NSTAGE - 1;
        if (nk < NT) {
            const uint32_t sn = sb0 + (uint32_t)(nk % NSTAGE) * STAGE_BYTES;
            CP_ASYNC16(sn + a_dst, a_src + nk * BK);
            CP_ASYNC16(sn + a_dst + 64 * RSB, a_src + (size_t)64 * K_DIM + nk * BK);
#pragma unroll
            for (int i = 0; i < 4; ++i)
                CP_ASYNC16(sn + b_dst + (uint32_t)i * 64 * RSB,
                           b_src + (size_t)i * 64 * K_DIM + nk * BK);
        }
        CP_COMMIT();

        // load ks1 fragments (same stage), then MMA ks0
#pragma unroll
        for (int mi = 0; mi < 4; ++mi)
            LDSM_X4(fa[1][mi], sa + a_lane + (uint32_t)mi * 16 * RSB + 32);
#pragma unroll
        for (int bi = 0; bi < 4; ++bi)
            LDSM_X4(fb[1][bi], sa + b_lane + (uint32_t)bi * 16 * RSB + 32);
#pragma unroll
        for (int mi = 0; mi < 4; ++mi)
#pragma unroll
            for (int bi = 0; bi < 4; ++bi) {
                MMA_F16(acc[mi][2 * bi],     fa[0][mi], fb[0][bi][0], fb[0][bi][2]);
                MMA_F16(acc[mi][2 * bi + 1], fa[0][mi], fb[0][bi][1], fb[0][bi][3]);
            }

        // stage kt+1 is resident after this wait
        CP_WAIT(NSTAGE - 2);
        __syncthreads();

        // prefetch next stage ks0 fragments, then MMA ks1
        const uint32_t sx = sb0 + (uint32_t)((kt + 1) % NSTAGE) * STAGE_BYTES;
#pragma unroll
        for (int mi = 0; mi < 4; ++mi)
            LDSM_X4(fa[0][mi], sx + a_lane + (uint32_t)mi * 16 * RSB);
#pragma unroll
        for (int bi = 0; bi < 4; ++bi)
            LDSM_X4(fb[0][bi], sx + b_lane + (uint32_t)bi * 16 * RSB);
#pragma unroll
        for (int mi = 0; mi < 4; ++mi)
#pragma unroll
            for (int bi = 0; bi < 4; ++bi) {
                MMA_F16(acc[mi][2 * bi],     fa[1][mi], fb[1][bi][0], fb[1][bi][2]);
                MMA_F16(acc[mi][2 * bi + 1], fa[1][mi], fb[1][bi][1], fb[1][bi][3]);
            }
    }

    // ---- epilogue: add bias, write fp32 (float4 stores) ----
    const int g = l >> 2;
    const int t = l & 3;
#pragma unroll
    for (int mi = 0; mi < 4; ++mi) {
        const int row0 = m0 + wm * 64 + mi * 16 + g;
        float* y0 = Y + (size_t)row0 * N_DIM;
#pragma unroll
        for (int ni = 0; ni < 8; ++ni) {
            const int col = n0 + wn * 64 + (ni >> 1) * 16 + (ni & 1) * 8 + 2 * t;
            const float2 bv = *(const float2*)(bias + col);
            float2 o0, o1;
            o0.x = acc[mi][ni][0] + bv.x;  o0.y = acc[mi][ni][1] + bv.y;
            o1.x = acc[mi][ni][2] + bv.x;  o1.y = acc[mi][ni][3] + bv.y;
            *(float2*)(y0 + col) = o0;
            *(float2*)(y0 + (size_t)8 * N_DIM + col) = o1;   // rows g+8
        }
    }
}

// ---------------------------------------------------------------------------
extern "C" void kernel_launch(void* const* d_in, const int* in_sizes, int n_in,
                              void* d_out, int out_size) {
    const float* x      = (const float*)d_in[0];
    const float* W      = (const float*)d_in[1];
    const float* bias   = (const float*)d_in[2];
    const float* w1a    = (const float*)d_in[3];
    const float* w1b    = (const float*)d_in[4];
    const float* w2a    = (const float*)d_in[5];
    const float* w2b    = (const float*)d_in[6];
    const float* scalar = (const float*)d_in[7];
    float* y = (float*)d_out;

    prologue_kernel<<<XBLK + WBLK, 256>>>(x, W, w1a, w1b, w2a, w2b, scalar);

    cudaFuncSetAttribute(gemm_f16_kernel,
                         cudaFuncAttributeMaxDynamicSharedMemorySize, SMEM_TOTAL);
    const int nblocks = (M_DIM / BM) * (N_DIM / BN);   // 1024
    gemm_f16_kernel<<<nblocks, 256, SMEM_TOTAL>>>(bias, y);
}

// round 16
// speedup vs baseline: 1.3738x; 1.0928x over previous
#include <cuda_runtime.h>
#include <cuda_fp16.h>
#include <cstdint>

// Problem constants
#define M_DIM 8192
#define N_DIM 4096
#define K_DIM 4096
#define RANK  16

// GEMM tiling: block 128x256, 8 warps, warp tile 64x64 (R5 exact)
#define BM 128
#define BN 256
#define BK 32
#define NT (K_DIM / BK)              // 128
#define NSTAGE 4
#define RS 40
#define RSB (RS * 2)                 // 80 bytes
#define A_ST_BYTES (BM * RSB)        // 10240
#define B_ST_BYTES (BN * RSB)        // 20480
#define STAGE_BYTES (A_ST_BYTES + B_ST_BYTES)   // 30720
#define SMEM_TOTAL (NSTAGE * STAGE_BYTES)       // 122880

// Pre-converted fp16 operands
__device__ __half g_xh[(size_t)M_DIM * K_DIM];
__device__ __half g_wh[(size_t)N_DIM * K_DIM];

// ---------------------------------------------------------------------------
__device__ __forceinline__ uint32_t smem_to_u32(const void* p) {
    uint32_t a;
    asm("{ .reg .u64 t; cvta.to.shared.u64 t, %1; cvt.u32.u64 %0, t; }" : "=r"(a) : "l"(p));
    return a;
}
#define CP_ASYNC16(dst, src) \
    asm volatile("cp.async.cg.shared.global [%0], [%1], 16;" :: "r"(dst), "l"(src))
#define CP_COMMIT() asm volatile("cp.async.commit_group;")
#define CP_WAIT(n)  asm volatile("cp.async.wait_group %0;" :: "n"(n))

#define LDSM_X4(r, addr) \
    asm volatile("ldmatrix.sync.aligned.m8n8.x4.shared.b16 {%0,%1,%2,%3}, [%4];" \
                 : "=r"((r)[0]), "=r"((r)[1]), "=r"((r)[2]), "=r"((r)[3]) : "r"(addr))

#define MMA_F16(d, a, b0, b1) \
    asm volatile("mma.sync.aligned.m16n8k16.row.col.f32.f16.f16.f32 " \
                 "{%0,%1,%2,%3}, {%4,%5,%6,%7}, {%8,%9}, {%0,%1,%2,%3};" \
                 : "+f"((d)[0]), "+f"((d)[1]), "+f"((d)[2]), "+f"((d)[3]) \
                 : "r"((a)[0]), "r"((a)[1]), "r"((a)[2]), "r"((a)[3]), "r"(b0), "r"(b1))

// ---------------------------------------------------------------------------
// Kernel 1 (merged prologue):
//   blocks [0, XBLK): convert x -> fp16 (DRAM-bound streaming)
//   blocks [XBLK, XBLK+FBLK): tiled rank-16 fold -> fp16 (64o x 64i per block)
// ---------------------------------------------------------------------------
#define XBLK ((int)(((size_t)M_DIM * K_DIM) / 4 / 256))   // 32768
#define FOT (N_DIM / 64)                                  // 64 o-tiles
#define FIT (K_DIM / 64)                                  // 64 i-tiles
#define FBLK (FOT * FIT)                                  // 4096 fold blocks

__global__ void prologue_kernel(const float* __restrict__ x,
                                const float* __restrict__ W,
                                const float* __restrict__ w1a,
                                const float* __restrict__ w1b,
                                const float* __restrict__ w2a,
                                const float* __restrict__ w2b,
                                const float* __restrict__ scalar) {
    if (blockIdx.x < XBLK) {
        size_t i = (size_t)(blockIdx.x * 256 + threadIdx.x) * 4;
        float4 v = *(const float4*)(x + i);
        __half2* o = (__half2*)(g_xh + i);
        o[0] = __floats2half2_rn(v.x, v.y);
        o[1] = __floats2half2_rn(v.z, v.w);
        return;
    }

    // ---- tiled fold: W_eff = W + (w1a@w1b)*(w2a@w2b)*scalar ----
    __shared__ float sa1[RANK][64], sa2[RANK][64];   // a transposed: [r][o]
    __shared__ float sb1[RANK][64], sb2[RANK][64];   // [r][i]
    const int fid = blockIdx.x - XBLK;
    const int o0 = (fid >> 6) * 64;       // o-tile base
    const int i0 = (fid & 63) * 64;       // i-tile base
    const int tid = threadIdx.x;

    // load a-tiles: thread (o = tid/4, r4 = tid%4) loads float4 along r, scatters
    {
        const int o = tid >> 2;
        const int r4 = (tid & 3) * 4;
        float4 a1 = *(const float4*)(w1a + (size_t)(o0 + o) * RANK + r4);
        float4 a2 = *(const float4*)(w2a + (size_t)(o0 + o) * RANK + r4);
        sa1[r4 + 0][o] = a1.x; sa1[r4 + 1][o] = a1.y; sa1[r4 + 2][o] = a1.z; sa1[r4 + 3][o] = a1.w;
        sa2[r4 + 0][o] = a2.x; sa2[r4 + 1][o] = a2.y; sa2[r4 + 2][o] = a2.z; sa2[r4 + 3][o] = a2.w;
    }
    // load b-tiles: thread (r = tid/16, c4 = tid%16) loads float4 along i
    {
        const int r = tid >> 4;
        const int c4 = (tid & 15) * 4;
        *(float4*)&sb1[r][c4] = *(const float4*)(w1b + (size_t)r * K_DIM + i0 + c4);
        *(float4*)&sb2[r][c4] = *(const float4*)(w2b + (size_t)r * K_DIM + i0 + c4);
    }
    __syncthreads();

    // compute: thread handles 4o x 4i
    const int ob = (tid >> 4) * 4;        // o_base (0..60)
    const int ib = (tid & 15) * 4;        // i_base (0..60)
    float4 s1[4] = {}, s2[4] = {};
#pragma unroll
    for (int r = 0; r < RANK; ++r) {
        const float4 b1 = *(const float4*)&sb1[r][ib];
        const float4 b2 = *(const float4*)&sb2[r][ib];
        const float4 a1 = *(const float4*)&sa1[r][ob];
        const float4 a2 = *(const float4*)&sa2[r][ob];
        const float a1v[4] = {a1.x, a1.y, a1.z, a1.w};
        const float a2v[4] = {a2.x, a2.y, a2.z, a2.w};
#pragma unroll
        for (int oj = 0; oj < 4; ++oj) {
            s1[oj].x += a1v[oj] * b1.x; s1[oj].y += a1v[oj] * b1.y;
            s1[oj].z += a1v[oj] * b1.z; s1[oj].w += a1v[oj] * b1.w;
            s2[oj].x += a2v[oj] * b2.x; s2[oj].y += a2v[oj] * b2.y;
            s2[oj].z += a2v[oj] * b2.z; s2[oj].w += a2v[oj] * b2.w;
        }
    }
    const float sc = scalar[0];
#pragma unroll
    for (int oj = 0; oj < 4; ++oj) {
        const size_t row = (size_t)(o0 + ob + oj) * K_DIM + i0 + ib;
        const float4 w = *(const float4*)(W + row);
        __half2* out = (__half2*)(g_wh + row);
        out[0] = __floats2half2_rn(w.x + s1[oj].x * s2[oj].x * sc,
                                   w.y + s1[oj].y * s2[oj].y * sc);
        out[1] = __floats2half2_rn(w.z + s1[oj].z * s2[oj].z * sc,
                                   w.w + s1[oj].w * s2[oj].w * sc);
    }
}

// ---------------------------------------------------------------------------
// Kernel 2: Y = Xh @ Wh^T + bias  (R5 exact: 256 thr, 2x4 warps, 64x64 tile)
// ---------------------------------------------------------------------------
__global__ void __launch_bounds__(256, 1)
gemm_f16_kernel(const float* __restrict__ bias, float* __restrict__ Y) {
    extern __shared__ char smem[];
    const uint32_t sb0 = smem_to_u32(smem);
    const int tid = threadIdx.x;
    const int l = tid & 31;
    const int warp = tid >> 5;
    const int wm = warp & 1;
    const int wn = warp >> 1;

    const int bid = blockIdx.x;
    const int sbt = bid >> 7;
    const int rr = bid & 127;
    const int m0 = ((sbt << 3) + (rr & 7)) * BM;
    const int n0 = (rr >> 3) * BN;

    const __half* Xg = g_xh + (size_t)m0 * K_DIM;
    const __half* Wg = g_wh + (size_t)n0 * K_DIM;

    const int crow = tid >> 2;
    const int cchk = tid & 3;
    const uint32_t a_dst = (uint32_t)crow * RSB + cchk * 16;
    const __half* a_src = Xg + (size_t)crow * K_DIM + cchk * 8;
    const uint32_t b_dst = A_ST_BYTES + (uint32_t)crow * RSB + cchk * 16;
    const __half* b_src = Wg + (size_t)crow * K_DIM + cchk * 8;

    const uint32_t lrow = l & 15;
    const uint32_t lkof = (uint32_t)(l >> 4) * 16;
    const uint32_t a_lane = (uint32_t)(wm * 64 + lrow) * RSB + lkof;
    const uint32_t b_lane = A_ST_BYTES + (uint32_t)(wn * 64 + lrow) * RSB + lkof;

    float acc[4][8][4];
#pragma unroll
    for (int a = 0; a < 4; ++a)
#pragma unroll
        for (int b = 0; b < 8; ++b)
#pragma unroll
            for (int c = 0; c < 4; ++c) acc[a][b][c] = 0.f;

#pragma unroll
    for (int s = 0; s < NSTAGE - 1; ++s) {
        const uint32_t sa = sb0 + s * STAGE_BYTES;
        CP_ASYNC16(sa + a_dst, a_src + s * BK);
        CP_ASYNC16(sa + a_dst + 64 * RSB, a_src + (size_t)64 * K_DIM + s * BK);
#pragma unroll
        for (int i = 0; i < 4; ++i)
            CP_ASYNC16(sa + b_dst + (uint32_t)i * 64 * RSB,
                       b_src + (size_t)i * 64 * K_DIM + s * BK);
        CP_COMMIT();
    }
    CP_WAIT(NSTAGE - 2);
    __syncthreads();

    uint32_t fa[2][4][4], fb[2][4][4];

#pragma unroll
    for (int mi = 0; mi < 4; ++mi)
        LDSM_X4(fa[0][mi], sb0 + a_lane + (uint32_t)mi * 16 * RSB);
#pragma unroll
    for (int bi = 0; bi < 4; ++bi)
        LDSM_X4(fb[0][bi], sb0 + b_lane + (uint32_t)bi * 16 * RSB);

    for (int kt = 0; kt < NT; ++kt) {
        const uint32_t sa = sb0 + (kt & (NSTAGE - 1)) * STAGE_BYTES;

        const int nk = kt + NSTAGE - 1;
        if (nk < NT) {
            const uint32_t sn = sb0 + (nk & (NSTAGE - 1)) * STAGE_BYTES;
            CP_ASYNC16(sn + a_dst, a_src + nk * BK);
            CP_ASYNC16(sn + a_dst + 64 * RSB, a_src + (size_t)64 * K_DIM + nk * BK);
#pragma unroll
            for (int i = 0; i < 4; ++i)
                CP_ASYNC16(sn + b_dst + (uint32_t)i * 64 * RSB,
                           b_src + (size_t)i * 64 * K_DIM + nk * BK);
        }
        CP_COMMIT();

#pragma unroll
        for (int mi = 0; mi < 4; ++mi)
            LDSM_X4(fa[1][mi], sa + a_lane + (uint32_t)mi * 16 * RSB + 32);
#pragma unroll
        for (int bi = 0; bi < 4; ++bi)
            LDSM_X4(fb[1][bi], sa + b_lane + (uint32_t)bi * 16 * RSB + 32);
#pragma unroll
        for (int mi = 0; mi < 4; ++mi)
#pragma unroll
            for (int bi = 0; bi < 4; ++bi) {
                MMA_F16(acc[mi][2 * bi],     fa[0][mi], fb[0][bi][0], fb[0][bi][2]);
                MMA_F16(acc[mi][2 * bi + 1], fa[0][mi], fb[0][bi][1], fb[0][bi][3]);
            }

        CP_WAIT(NSTAGE - 2);
        __syncthreads();

        const uint32_t sx = sb0 + ((kt + 1) & (NSTAGE - 1)) * STAGE_BYTES;
#pragma unroll
        for (int mi = 0; mi < 4; ++mi)
            LDSM_X4(fa[0][mi], sx + a_lane + (uint32_t)mi * 16 * RSB);
#pragma unroll
        for (int bi = 0; bi < 4; ++bi)
            LDSM_X4(fb[0][bi], sx + b_lane + (uint32_t)bi * 16 * RSB);
#pragma unroll
        for (int mi = 0; mi < 4; ++mi)
#pragma unroll
            for (int bi = 0; bi < 4; ++bi) {
                MMA_F16(acc[mi][2 * bi],     fa[1][mi], fb[1][bi][0], fb[1][bi][2]);
                MMA_F16(acc[mi][2 * bi + 1], fa[1][mi], fb[1][bi][1], fb[1][bi][3]);
            }
    }

    const int g = l >> 2;
    const int t = l & 3;
#pragma unroll
    for (int mi = 0; mi < 4; ++mi) {
        const int row0 = m0 + wm * 64 + mi * 16 + g;
        float* y0 = Y + (size_t)row0 * N_DIM;
#pragma unroll
        for (int ni = 0; ni < 8; ++ni) {
            const int col = n0 + wn * 64 + (ni >> 1) * 16 + (ni & 1) * 8 + 2 * t;
            const float2 bv = *(const float2*)(bias + col);
            float2 o0, o1;
            o0.x = acc[mi][ni][0] + bv.x;  o0.y = acc[mi][ni][1] + bv.y;
            o1.x = acc[mi][ni][2] + bv.x;  o1.y = acc[mi][ni][3] + bv.y;
            *(float2*)(y0 + col) = o0;
            *(float2*)(y0 + (size_t)8 * N_DIM + col) = o1;
        }
    }
}

// ---------------------------------------------------------------------------
extern "C" void kernel_launch(void* const* d_in, const int* in_sizes, int n_in,
                              void* d_out, int out_size) {
    const float* x      = (const float*)d_in[0];
    const float* W      = (const float*)d_in[1];
    const float* bias   = (const float*)d_in[2];
    const float* w1a    = (const float*)d_in[3];
    const float* w1b    = (const float*)d_in[4];
    const float* w2a    = (const float*)d_in[5];
    const float* w2b    = (const float*)d_in[6];
    const float* scalar = (const float*)d_in[7];
    float* y = (float*)d_out;

    prologue_kernel<<<XBLK + FBLK, 256>>>(x, W, w1a, w1b, w2a, w2b, scalar);

    cudaFuncSetAttribute(gemm_f16_kernel,
                         cudaFuncAttributeMaxDynamicSharedMemorySize, SMEM_TOTAL);
    const int nblocks = (M_DIM / BM) * (N_DIM / BN);   // 1024
    gemm_f16_kernel<<<nblocks, 256, SMEM_TOTAL>>>(bias, y);
}